// round 14
// baseline (speedup 1.0000x reference)
#include <cuda_runtime.h>
#include <math.h>

#define B1N 48
#define B2N 48
#define RN 36
#define LN 30
#define DN 1024
#define HN 4
#define EPSV 1e-8f
#define SM 1728           // B1N*RN
#define SN 1440           // B2N*LN

// Scratch (static device globals: allocation-free)
__device__ float g_k1[B1N * RN * DN];  // v1 @ w_img^T
__device__ float g_k2[B2N * LN * DN];  // v2 @ w_txt^T
__device__ float g_Vb[B1N * RN * DN];  // v1 @ w1b^T
__device__ float g_Va[B2N * LN * DN];  // v2 @ w1a^T
__device__ float g_S [SM * SN];        // k1_flat @ k2_flat^T / 32

// ---------------------------------------------------------------------------
// 128x128 tile, k=16 depth, 8x8 per-thread NT GEMM core with register
// double-buffering: next k-tile's global loads are issued BEFORE the compute
// block so the ~600-cycle FMA burst hides L2/DRAM latency.
// ---------------------------------------------------------------------------
#define GT 128
#define GK 16
#define GP 132

__device__ __forceinline__ void gemm_core(
    const float* __restrict__ A, const float* __restrict__ B, float* __restrict__ C,
    int M, int N, float scale, int row0, int col0)
{
    __shared__ __align__(16) float As[GK][GP];
    __shared__ __align__(16) float Bs[GK][GP];

    const int tid = threadIdx.x;
    const int lr = tid >> 1;            // 0..127
    const int lk = (tid & 1) << 3;      // 0 or 8
    const int tx = tid & 15, ty = tid >> 4;

    float acc[8][8];
#pragma unroll
    for (int i = 0; i < 8; i++)
#pragma unroll
        for (int j = 0; j < 8; j++) acc[i][j] = 0.f;

    const int arow = row0 + lr;
    const int brow = col0 + lr;
    const bool aval = arow < M;
    const bool bval = brow < N;
    const float4 z4 = make_float4(0.f, 0.f, 0.f, 0.f);
    const float* aptr = A + (size_t)arow * DN + lk;
    const float* bptr = B + (size_t)brow * DN + lk;

    // prefetch k0 = 0
    float4 a0 = z4, a1 = z4, b0 = z4, b1 = z4;
    if (aval) { a0 = *(const float4*)(aptr); a1 = *(const float4*)(aptr + 4); }
    if (bval) { b0 = *(const float4*)(bptr); b1 = *(const float4*)(bptr + 4); }

    for (int k0 = 0; k0 < DN; k0 += GK) {
        __syncthreads();
        As[lk + 0][lr] = a0.x; As[lk + 1][lr] = a0.y; As[lk + 2][lr] = a0.z; As[lk + 3][lr] = a0.w;
        As[lk + 4][lr] = a1.x; As[lk + 5][lr] = a1.y; As[lk + 6][lr] = a1.z; As[lk + 7][lr] = a1.w;
        Bs[lk + 0][lr] = b0.x; Bs[lk + 1][lr] = b0.y; Bs[lk + 2][lr] = b0.z; Bs[lk + 3][lr] = b0.w;
        Bs[lk + 4][lr] = b1.x; Bs[lk + 5][lr] = b1.y; Bs[lk + 6][lr] = b1.z; Bs[lk + 7][lr] = b1.w;
        __syncthreads();

        // issue next tile's loads NOW; they retire during the compute below
        if (k0 + GK < DN) {
            const float* ap = aptr + k0 + GK;
            const float* bp = bptr + k0 + GK;
            if (aval) { a0 = *(const float4*)(ap); a1 = *(const float4*)(ap + 4); }
            if (bval) { b0 = *(const float4*)(bp); b1 = *(const float4*)(bp + 4); }
        }

#pragma unroll
        for (int k = 0; k < GK; k++) {
            float4 al = *(const float4*)&As[k][ty << 3];
            float4 ah = *(const float4*)&As[k][(ty << 3) + 4];
            float4 bl = *(const float4*)&Bs[k][tx << 3];
            float4 bh = *(const float4*)&Bs[k][(tx << 3) + 4];
            float ar[8] = {al.x, al.y, al.z, al.w, ah.x, ah.y, ah.z, ah.w};
            float br[8] = {bl.x, bl.y, bl.z, bl.w, bh.x, bh.y, bh.z, bh.w};
#pragma unroll
            for (int i = 0; i < 8; i++)
#pragma unroll
                for (int j = 0; j < 8; j++) acc[i][j] += ar[i] * br[j];
        }
    }
#pragma unroll
    for (int i = 0; i < 8; i++) {
        int r = row0 + (ty << 3) + i;
        if (r < M) {
            int c = col0 + (tx << 3);
            if (c < N) {
                *(float4*)(C + (size_t)r * N + c) =
                    make_float4(acc[i][0] * scale, acc[i][1] * scale,
                                acc[i][2] * scale, acc[i][3] * scale);
                *(float4*)(C + (size_t)r * N + c + 4) =
                    make_float4(acc[i][4] * scale, acc[i][5] * scale,
                                acc[i][6] * scale, acc[i][7] * scale);
            }
        }
    }
}

// 4 fused pre-GEMMs: z=0: g_k1=v1@wimg^T  z=1: g_Vb=v1@w1b^T
//                    z=2: g_k2=v2@wtxt^T  z=3: g_Va=v2@w1a^T   (all N=1024)
__global__ __launch_bounds__(256) void gemm_pre4_kernel(
    const float* __restrict__ v1, const float* __restrict__ v2,
    const float* __restrict__ wimg, const float* __restrict__ wtxt,
    const float* __restrict__ w1a, const float* __restrict__ w1b)
{
    const int z = blockIdx.z;
    const float* A = (z < 2) ? v1 : v2;
    const float* B = (z == 0) ? wimg : (z == 1) ? w1b : (z == 2) ? wtxt : w1a;
    float* C = (z == 0) ? g_k1 : (z == 1) ? g_Vb : (z == 2) ? g_k2 : g_Va;
    const int M = (z < 2) ? SM : SN;
    const int row0 = blockIdx.y * GT;
    if (row0 >= M) return;
    gemm_core(A, B, C, M, DN, 1.0f, row0, blockIdx.x * GT);
}

// S-GEMM: g_S[1728,1440] = g_k1_flat @ g_k2_flat^T / 32
__global__ __launch_bounds__(256) void gemm_s_kernel()
{
    gemm_core(g_k1, g_k2, g_S, SM, SN, 0.03125f, blockIdx.y * GT, blockIdx.x * GT);
}

// ---------------------------------------------------------------------------
// One block per (a,b) pair. 256 threads. Phase 1 replaced by g_S load.
// ---------------------------------------------------------------------------
__global__ __launch_bounds__(256) void pair_kernel(
    const float* __restrict__ v1, const float* __restrict__ v2,
    const float* __restrict__ w2a, const float* __restrict__ b1a,
    const float* __restrict__ b2a, const float* __restrict__ w2b,
    const float* __restrict__ b1b, const float* __restrict__ b2b,
    float* __restrict__ out)
{
    const int a = blockIdx.y, b = blockIdx.x;
    const int tid = threadIdx.x;
    const int lane = tid & 31, wid = tid >> 5;

    __shared__ __align__(16) float Ssm[RN][33];
    __shared__ __align__(16) float p2s[40][32];   // softmax over l, rows r (padded)
    __shared__ __align__(16) float p1s[32][40];   // softmax over r, rows l (padded)
    __shared__ __align__(16) float stage[5280];   // phase-3 staging
    __shared__ float s_a[40][HN];
    __shared__ float s_b[32][HN];
    __shared__ float p_a[HN][RN];
    __shared__ float p_b[HN][LN];
    __shared__ float qa[RN];
    __shared__ float qb[LN];
    __shared__ float qbar_a[LN];
    __shared__ float qbar_b[RN];
    __shared__ float red[24];

    // zero padded probability matrices (pad rows/cols must stay exactly 0)
    for (int i = tid; i < 40 * 32; i += 256) ((float*)p2s)[i] = 0.f;
    for (int i = tid; i < 32 * 40; i += 256) ((float*)p1s)[i] = 0.f;

    // ---------------- phase 1': load S tile from g_S -------------------------
    for (int i = tid; i < RN * LN; i += 256) {
        int r = i / LN, l = i - r * LN;
        Ssm[r][l] = g_S[(size_t)(a * RN + r) * SN + b * LN + l];
    }
    __syncthreads();

    // ---------------- phase 2: the two attention softmaxes -------------------
    if (tid < RN) {  // rows -> p2[r][l]
        int r = tid;
        float m = -1e30f;
        for (int l = 0; l < LN; l++) m = fmaxf(m, Ssm[r][l]);
        float s = 0.f;
        for (int l = 0; l < LN; l++) s += __expf(Ssm[r][l] - m);
        float inv = 1.f / s;
        for (int l = 0; l < LN; l++) p2s[r][l] = __expf(Ssm[r][l] - m) * inv;
    }
    if (tid >= 64 && tid < 64 + LN) {  // cols -> p1[l][r]
        int l = tid - 64;
        float m = -1e30f;
        for (int r = 0; r < RN; r++) m = fmaxf(m, Ssm[r][l]);
        float s = 0.f;
        for (int r = 0; r < RN; r++) s += __expf(Ssm[r][l] - m);
        float inv = 1.f / s;
        for (int r = 0; r < RN; r++) p1s[l][r] = __expf(Ssm[r][l] - m) * inv;
    }

    // ---------------- phase 3a: s_a[r][h] = sum_e relu(P2@Va + b1a) * w2a ----
    const float* Vap = g_Va + (size_t)b * LN * DN;
    float sacc[5][HN];
#pragma unroll
    for (int i = 0; i < 5; i++)
#pragma unroll
        for (int j = 0; j < HN; j++) sacc[i][j] = 0.f;
    const int R0 = wid * 5;

    for (int j = 0; j < 8; j++) {
        __syncthreads();
        for (int s = tid; s < 1024; s += 256) {   // stage Va[32][132], rows>=30 zeroed
            int l = s >> 5, c4 = (s & 31) << 2;
            float4 v = make_float4(0.f, 0.f, 0.f, 0.f);
            if (l < LN) v = *(const float4*)(Vap + (size_t)l * DN + (j << 7) + c4);
            float* dst = stage + l * 132 + c4;
            dst[0] = v.x; dst[1] = v.y; dst[2] = v.z; dst[3] = v.w;
        }
        __syncthreads();
        const int e0 = (j << 7) + (lane << 2);
        float4 bb = *(const float4*)(b1a + e0);
        float h[5][4];
#pragma unroll
        for (int r5 = 0; r5 < 5; r5++) {
            h[r5][0] = bb.x; h[r5][1] = bb.y; h[r5][2] = bb.z; h[r5][3] = bb.w;
        }
#pragma unroll
        for (int l4 = 0; l4 < 8; l4++) {
            float4 va[4];
#pragma unroll
            for (int il = 0; il < 4; il++)
                va[il] = *(const float4*)&stage[(l4 * 4 + il) * 132 + (lane << 2)];
#pragma unroll
            for (int r5 = 0; r5 < 5; r5++) {
                float4 p = *(const float4*)&p2s[R0 + r5][l4 << 2];
                h[r5][0] += p.x * va[0].x + p.y * va[1].x + p.z * va[2].x + p.w * va[3].x;
                h[r5][1] += p.x * va[0].y + p.y * va[1].y + p.z * va[2].y + p.w * va[3].y;
                h[r5][2] += p.x * va[0].z + p.y * va[1].z + p.z * va[2].z + p.w * va[3].z;
                h[r5][3] += p.x * va[0].w + p.y * va[1].w + p.z * va[2].w + p.w * va[3].w;
            }
        }
        float4 w0 = *(const float4*)(w2a + 0 * DN + e0);
        float4 w1 = *(const float4*)(w2a + 1 * DN + e0);
        float4 w2 = *(const float4*)(w2a + 2 * DN + e0);
        float4 w3 = *(const float4*)(w2a + 3 * DN + e0);
#pragma unroll
        for (int r5 = 0; r5 < 5; r5++) {
            float h0 = fmaxf(h[r5][0], 0.f), h1 = fmaxf(h[r5][1], 0.f);
            float h2 = fmaxf(h[r5][2], 0.f), h3 = fmaxf(h[r5][3], 0.f);
            sacc[r5][0] += h0 * w0.x + h1 * w0.y + h2 * w0.z + h3 * w0.w;
            sacc[r5][1] += h0 * w1.x + h1 * w1.y + h2 * w1.z + h3 * w1.w;
            sacc[r5][2] += h0 * w2.x + h1 * w2.y + h2 * w2.z + h3 * w2.w;
            sacc[r5][3] += h0 * w3.x + h1 * w3.y + h2 * w3.z + h3 * w3.w;
        }
    }
#pragma unroll
    for (int r5 = 0; r5 < 5; r5++)
#pragma unroll
        for (int hh = 0; hh < HN; hh++) {
            float v = sacc[r5][hh];
#pragma unroll
            for (int off = 16; off; off >>= 1) v += __shfl_xor_sync(0xffffffffu, v, off);
            if (lane == 0) s_a[R0 + r5][hh] = v + b2a[hh];
        }

    // ---------------- phase 3b: mirror for words ------------------------------
    const float* Vbp = g_Vb + (size_t)a * RN * DN;
    float sbac[4][HN];
#pragma unroll
    for (int i = 0; i < 4; i++)
#pragma unroll
        for (int j = 0; j < HN; j++) sbac[i][j] = 0.f;
    const int L0 = wid * 4;

    for (int j = 0; j < 8; j++) {
        __syncthreads();
        for (int s = tid; s < 1280; s += 256) {   // stage Vb[40][132], rows>=36 zeroed
            int r = s >> 5, c4 = (s & 31) << 2;
            float4 v = make_float4(0.f, 0.f, 0.f, 0.f);
            if (r < RN) v = *(const float4*)(Vbp + (size_t)r * DN + (j << 7) + c4);
            float* dst = stage + r * 132 + c4;
            dst[0] = v.x; dst[1] = v.y; dst[2] = v.z; dst[3] = v.w;
        }
        __syncthreads();
        const int e0 = (j << 7) + (lane << 2);
        float4 bb = *(const float4*)(b1b + e0);
        float h[4][4];
#pragma unroll
        for (int l4 = 0; l4 < 4; l4++) {
            h[l4][0] = bb.x; h[l4][1] = bb.y; h[l4][2] = bb.z; h[l4][3] = bb.w;
        }
#pragma unroll
        for (int r4 = 0; r4 < 10; r4++) {
            float4 vb[4];
#pragma unroll
            for (int il = 0; il < 4; il++)
                vb[il] = *(const float4*)&stage[(r4 * 4 + il) * 132 + (lane << 2)];
#pragma unroll
            for (int l4 = 0; l4 < 4; l4++) {
                float4 p = *(const float4*)&p1s[L0 + l4][r4 << 2];
                h[l4][0] += p.x * vb[0].x + p.y * vb[1].x + p.z * vb[2].x + p.w * vb[3].x;
                h[l4][1] += p.x * vb[0].y + p.y * vb[1].y + p.z * vb[2].y + p.w * vb[3].y;
                h[l4][2] += p.x * vb[0].z + p.y * vb[1].z + p.z * vb[2].z + p.w * vb[3].z;
                h[l4][3] += p.x * vb[0].w + p.y * vb[1].w + p.z * vb[2].w + p.w * vb[3].w;
            }
        }
        float4 w0 = *(const float4*)(w2b + 0 * DN + e0);
        float4 w1 = *(const float4*)(w2b + 1 * DN + e0);
        float4 w2 = *(const float4*)(w2b + 2 * DN + e0);
        float4 w3 = *(const float4*)(w2b + 3 * DN + e0);
#pragma unroll
        for (int l4 = 0; l4 < 4; l4++) {
            float h0 = fmaxf(h[l4][0], 0.f), h1 = fmaxf(h[l4][1], 0.f);
            float h2 = fmaxf(h[l4][2], 0.f), h3 = fmaxf(h[l4][3], 0.f);
            sbac[l4][0] += h0 * w0.x + h1 * w0.y + h2 * w0.z + h3 * w0.w;
            sbac[l4][1] += h0 * w1.x + h1 * w1.y + h2 * w1.z + h3 * w1.w;
            sbac[l4][2] += h0 * w2.x + h1 * w2.y + h2 * w2.z + h3 * w2.w;
            sbac[l4][3] += h0 * w3.x + h1 * w3.y + h2 * w3.z + h3 * w3.w;
        }
    }
#pragma unroll
    for (int l4 = 0; l4 < 4; l4++)
#pragma unroll
        for (int hh = 0; hh < HN; hh++) {
            float v = sbac[l4][hh];
#pragma unroll
            for (int off = 16; off; off >>= 1) v += __shfl_xor_sync(0xffffffffu, v, off);
            if (lane == 0) s_b[L0 + l4][hh] = v + b2b[hh];
        }
    __syncthreads();

    // ---------------- phase 4: head softmax + combine weights -----------------
    if (tid < HN) {
        int hh = tid;
        float m = -1e30f;
        for (int n = 0; n < RN; n++) m = fmaxf(m, s_a[n][hh]);
        float s = 0.f;
        for (int n = 0; n < RN; n++) s += __expf(s_a[n][hh] - m);
        float inv = 1.f / s;
        for (int n = 0; n < RN; n++) p_a[hh][n] = __expf(s_a[n][hh] - m) * inv;
    }
    if (tid >= 32 && tid < 32 + HN) {
        int hh = tid - 32;
        float m = -1e30f;
        for (int n = 0; n < LN; n++) m = fmaxf(m, s_b[n][hh]);
        float s = 0.f;
        for (int n = 0; n < LN; n++) s += __expf(s_b[n][hh] - m);
        float inv = 1.f / s;
        for (int n = 0; n < LN; n++) p_b[hh][n] = __expf(s_b[n][hh] - m) * inv;
    }
    __syncthreads();
    if (tid < RN)
        qa[tid] = 0.25f * (p_a[0][tid] + p_a[1][tid] + p_a[2][tid] + p_a[3][tid]);
    if (tid >= 64 && tid < 64 + LN) {
        int l = tid - 64;
        qb[l] = 0.25f * (p_b[0][l] + p_b[1][l] + p_b[2][l] + p_b[3][l]);
    }
    __syncthreads();
    if (tid < LN) {
        float s = 0.f;
        for (int n = 0; n < RN; n++) s += qa[n] * p2s[n][tid];
        qbar_a[tid] = s;
    }
    if (tid >= 32 && tid < 32 + RN) {
        int r = tid - 32;
        float s = 0.f;
        for (int l = 0; l < LN; l++) s += qb[l] * p1s[l][r];
        qbar_b[r] = s;
    }
    __syncthreads();

    // ---------------- phase 5: u_a = qbar_a@v2[b], u_b = qbar_b@v1[a], cosine -
    const float* v2p = v2 + (size_t)b * LN * DN;
    const float* v1p = v1 + (size_t)a * RN * DN;
    const int e0 = tid << 2;
    float4 ua = make_float4(0.f, 0.f, 0.f, 0.f);
    float4 ub = make_float4(0.f, 0.f, 0.f, 0.f);
    for (int l = 0; l < LN; l++) {
        float q = qbar_a[l];
        float4 v = *(const float4*)(v2p + (size_t)l * DN + e0);
        ua.x += q * v.x; ua.y += q * v.y; ua.z += q * v.z; ua.w += q * v.w;
    }
    for (int r = 0; r < RN; r++) {
        float q = qbar_b[r];
        float4 v = *(const float4*)(v1p + (size_t)r * DN + e0);
        ub.x += q * v.x; ub.y += q * v.y; ub.z += q * v.z; ub.w += q * v.w;
    }
    float da = ua.x * ub.x + ua.y * ub.y + ua.z * ub.z + ua.w * ub.w;
    float na = ua.x * ua.x + ua.y * ua.y + ua.z * ua.z + ua.w * ua.w;
    float nb = ub.x * ub.x + ub.y * ub.y + ub.z * ub.z + ub.w * ub.w;
#pragma unroll
    for (int off = 16; off; off >>= 1) {
        da += __shfl_xor_sync(0xffffffffu, da, off);
        na += __shfl_xor_sync(0xffffffffu, na, off);
        nb += __shfl_xor_sync(0xffffffffu, nb, off);
    }
    if (lane == 0) { red[wid] = da; red[8 + wid] = na; red[16 + wid] = nb; }
    __syncthreads();
    if (tid == 0) {
        float D = 0.f, Na = 0.f, Nb = 0.f;
        for (int w = 0; w < 8; w++) { D += red[w]; Na += red[8 + w]; Nb += red[16 + w]; }
        out[a * B2N + b] = D / ((sqrtf(Na) + EPSV) * (sqrtf(Nb) + EPSV));
    }
}

extern "C" void kernel_launch(void* const* d_in, const int* in_sizes, int n_in,
                              void* d_out, int out_size) {
    const float* v1   = (const float*)d_in[0];
    const float* v2   = (const float*)d_in[1];
    const float* wimg = (const float*)d_in[2];
    const float* wtxt = (const float*)d_in[3];
    const float* w1a  = (const float*)d_in[4];
    const float* b1a  = (const float*)d_in[5];
    const float* w2a  = (const float*)d_in[6];
    const float* b2a  = (const float*)d_in[7];
    const float* w1b  = (const float*)d_in[8];
    const float* b1b  = (const float*)d_in[9];
    const float* w2b  = (const float*)d_in[10];
    const float* b2b  = (const float*)d_in[11];
    float* out = (float*)d_out;

    // 1) 4 fused pre-GEMMs (N=1024): grid z picks operand set
    dim3 gp(DN / GT, (SM + GT - 1) / GT, 4);          // (8, 14, 4)
    gemm_pre4_kernel<<<gp, 256>>>(v1, v2, wimg, wtxt, w1a, w1b);

    // 2) S-GEMM: g_S = g_k1 @ g_k2^T / 32
    dim3 gs((SN + GT - 1) / GT, (SM + GT - 1) / GT);  // (12, 14)
    gemm_s_kernel<<<gs, 256>>>();

    // 3) per-pair kernel
    pair_kernel<<<dim3(B2N, B1N), 256>>>(v1, v2, w2a, b1a, b2a, w2b, b1b, b2b, out);
    (void)in_sizes; (void)n_in; (void)out_size;
}

// round 16
// speedup vs baseline: 1.0331x; 1.0331x over previous
#include <cuda_runtime.h>
#include <math.h>

#define B1N 48
#define B2N 48
#define RN 36
#define LN 30
#define DN 1024
#define HN 4
#define EPSV 1e-8f
#define SM 1728           // B1N*RN
#define SN 1440           // B2N*LN

// Scratch (static device globals: allocation-free)
__device__ float g_k1[B1N * RN * DN];  // v1 @ w_img^T
__device__ float g_k2[B2N * LN * DN];  // v2 @ w_txt^T
__device__ float g_Vb[B1N * RN * DN];  // v1 @ w1b^T
__device__ float g_Va[B2N * LN * DN];  // v2 @ w1a^T
__device__ float g_S [SM * SN];        // k1_flat @ k2_flat^T / 32

typedef unsigned long long u64t;

// packed f32x2 helpers (sm_103a FFMA2 path — ptxas never emits this itself)
__device__ __forceinline__ u64t pack_dup(float x) {
    u64t r; asm("mov.b64 %0, {%1, %1};" : "=l"(r) : "f"(x)); return r;
}
__device__ __forceinline__ void ffma2(u64t& d, u64t a, u64t b) {
    asm("fma.rn.f32x2 %0, %1, %2, %0;" : "+l"(d) : "l"(a), "l"(b));
}
__device__ __forceinline__ void unpack2(float& lo, float& hi, u64t v) {
    asm("mov.b64 {%0, %1}, %2;" : "=f"(lo), "=f"(hi) : "l"(v));
}

// ---------------------------------------------------------------------------
// 128x128 tile, k=16 depth, 8x8 per-thread NT GEMM core. Inner product uses
// packed fma.rn.f32x2: 32 FFMA2 per k-step (vs 64 half-rate FFMA) -> 2x on
// the binding FMA pipe. __launch_bounds__(256,2) pins >=2 CTAs/SM.
// ---------------------------------------------------------------------------
#define GT 128
#define GK 16
#define GP 132

__device__ __forceinline__ void gemm_core(
    const float* __restrict__ A, const float* __restrict__ B, float* __restrict__ C,
    int M, int N, float scale, int row0, int col0)
{
    __shared__ __align__(16) float As[GK][GP];
    __shared__ __align__(16) float Bs[GK][GP];

    const int tid = threadIdx.x;
    const int lr = tid >> 1;            // 0..127
    const int lk = (tid & 1) << 3;      // 0 or 8
    const int tx = tid & 15, ty = tid >> 4;

    u64t acc2[8][4];                    // [row][col-pair], each holds 2 fp32 cols
#pragma unroll
    for (int i = 0; i < 8; i++)
#pragma unroll
        for (int j = 0; j < 4; j++) acc2[i][j] = 0ull;

    const int arow = row0 + lr;
    const int brow = col0 + lr;
    const bool aval = arow < M;
    const bool bval = brow < N;
    const float4 z4 = make_float4(0.f, 0.f, 0.f, 0.f);

    for (int k0 = 0; k0 < DN; k0 += GK) {
        float4 av0 = z4, av1 = z4, bv0 = z4, bv1 = z4;
        if (aval) {
            av0 = *(const float4*)(A + (size_t)arow * DN + k0 + lk);
            av1 = *(const float4*)(A + (size_t)arow * DN + k0 + lk + 4);
        }
        if (bval) {
            bv0 = *(const float4*)(B + (size_t)brow * DN + k0 + lk);
            bv1 = *(const float4*)(B + (size_t)brow * DN + k0 + lk + 4);
        }
        __syncthreads();
        As[lk + 0][lr] = av0.x; As[lk + 1][lr] = av0.y; As[lk + 2][lr] = av0.z; As[lk + 3][lr] = av0.w;
        As[lk + 4][lr] = av1.x; As[lk + 5][lr] = av1.y; As[lk + 6][lr] = av1.z; As[lk + 7][lr] = av1.w;
        Bs[lk + 0][lr] = bv0.x; Bs[lk + 1][lr] = bv0.y; Bs[lk + 2][lr] = bv0.z; Bs[lk + 3][lr] = bv0.w;
        Bs[lk + 4][lr] = bv1.x; Bs[lk + 5][lr] = bv1.y; Bs[lk + 6][lr] = bv1.z; Bs[lk + 7][lr] = bv1.w;
        __syncthreads();

#pragma unroll
        for (int k = 0; k < GK; k++) {
            float4 al = *(const float4*)&As[k][ty << 3];
            float4 ah = *(const float4*)&As[k][(ty << 3) + 4];
            // B pairs read directly as packed 64-bit lanes (16B-aligned rows)
            ulonglong2 bl2 = *(const ulonglong2*)&Bs[k][tx << 3];
            ulonglong2 bh2 = *(const ulonglong2*)&Bs[k][(tx << 3) + 4];
            u64t b2[4] = {bl2.x, bl2.y, bh2.x, bh2.y};
            float ar[8] = {al.x, al.y, al.z, al.w, ah.x, ah.y, ah.z, ah.w};
#pragma unroll
            for (int i = 0; i < 8; i++) {
                u64t ad = pack_dup(ar[i]);
#pragma unroll
                for (int jp = 0; jp < 4; jp++) ffma2(acc2[i][jp], ad, b2[jp]);
            }
        }
    }
#pragma unroll
    for (int i = 0; i < 8; i++) {
        int r = row0 + (ty << 3) + i;
        if (r < M) {
            int c = col0 + (tx << 3);
            if (c < N) {
                float cv[8];
#pragma unroll
                for (int jp = 0; jp < 4; jp++)
                    unpack2(cv[2 * jp], cv[2 * jp + 1], acc2[i][jp]);
                *(float4*)(C + (size_t)r * N + c) =
                    make_float4(cv[0] * scale, cv[1] * scale, cv[2] * scale, cv[3] * scale);
                *(float4*)(C + (size_t)r * N + c + 4) =
                    make_float4(cv[4] * scale, cv[5] * scale, cv[6] * scale, cv[7] * scale);
            }
        }
    }
}

// 4 fused pre-GEMMs: z=0: g_k1=v1@wimg^T  z=1: g_Vb=v1@w1b^T
//                    z=2: g_k2=v2@wtxt^T  z=3: g_Va=v2@w1a^T   (all N=1024)
__global__ __launch_bounds__(256, 2) void gemm_pre4_kernel(
    const float* __restrict__ v1, const float* __restrict__ v2,
    const float* __restrict__ wimg, const float* __restrict__ wtxt,
    const float* __restrict__ w1a, const float* __restrict__ w1b)
{
    const int z = blockIdx.z;
    const float* A = (z < 2) ? v1 : v2;
    const float* B = (z == 0) ? wimg : (z == 1) ? w1b : (z == 2) ? wtxt : w1a;
    float* C = (z == 0) ? g_k1 : (z == 1) ? g_Vb : (z == 2) ? g_k2 : g_Va;
    const int M = (z < 2) ? SM : SN;
    const int row0 = blockIdx.y * GT;
    if (row0 >= M) return;
    gemm_core(A, B, C, M, DN, 1.0f, row0, blockIdx.x * GT);
}

// S-GEMM: g_S[1728,1440] = g_k1_flat @ g_k2_flat^T / 32
__global__ __launch_bounds__(256, 2) void gemm_s_kernel()
{
    gemm_core(g_k1, g_k2, g_S, SM, SN, 0.03125f, blockIdx.y * GT, blockIdx.x * GT);
}

// ---------------------------------------------------------------------------
// One block per (a,b) pair. 256 threads. Phase 1 replaced by g_S load.
// ---------------------------------------------------------------------------
__global__ __launch_bounds__(256) void pair_kernel(
    const float* __restrict__ v1, const float* __restrict__ v2,
    const float* __restrict__ w2a, const float* __restrict__ b1a,
    const float* __restrict__ b2a, const float* __restrict__ w2b,
    const float* __restrict__ b1b, const float* __restrict__ b2b,
    float* __restrict__ out)
{
    const int a = blockIdx.y, b = blockIdx.x;
    const int tid = threadIdx.x;
    const int lane = tid & 31, wid = tid >> 5;

    __shared__ __align__(16) float Ssm[RN][33];
    __shared__ __align__(16) float p2s[40][32];   // softmax over l, rows r (padded)
    __shared__ __align__(16) float p1s[32][40];   // softmax over r, rows l (padded)
    __shared__ __align__(16) float stage[5280];   // phase-3 staging
    __shared__ float s_a[40][HN];
    __shared__ float s_b[32][HN];
    __shared__ float p_a[HN][RN];
    __shared__ float p_b[HN][LN];
    __shared__ float qa[RN];
    __shared__ float qb[LN];
    __shared__ float qbar_a[LN];
    __shared__ float qbar_b[RN];
    __shared__ float red[24];

    // zero padded probability matrices (pad rows/cols must stay exactly 0)
    for (int i = tid; i < 40 * 32; i += 256) ((float*)p2s)[i] = 0.f;
    for (int i = tid; i < 32 * 40; i += 256) ((float*)p1s)[i] = 0.f;

    // ---------------- phase 1': load S tile from g_S -------------------------
    for (int i = tid; i < RN * LN; i += 256) {
        int r = i / LN, l = i - r * LN;
        Ssm[r][l] = g_S[(size_t)(a * RN + r) * SN + b * LN + l];
    }
    __syncthreads();

    // ---------------- phase 2: the two attention softmaxes -------------------
    if (tid < RN) {  // rows -> p2[r][l]
        int r = tid;
        float m = -1e30f;
        for (int l = 0; l < LN; l++) m = fmaxf(m, Ssm[r][l]);
        float s = 0.f;
        for (int l = 0; l < LN; l++) s += __expf(Ssm[r][l] - m);
        float inv = 1.f / s;
        for (int l = 0; l < LN; l++) p2s[r][l] = __expf(Ssm[r][l] - m) * inv;
    }
    if (tid >= 64 && tid < 64 + LN) {  // cols -> p1[l][r]
        int l = tid - 64;
        float m = -1e30f;
        for (int r = 0; r < RN; r++) m = fmaxf(m, Ssm[r][l]);
        float s = 0.f;
        for (int r = 0; r < RN; r++) s += __expf(Ssm[r][l] - m);
        float inv = 1.f / s;
        for (int r = 0; r < RN; r++) p1s[l][r] = __expf(Ssm[r][l] - m) * inv;
    }

    // ---------------- phase 3a: s_a[r][h] = sum_e relu(P2@Va + b1a) * w2a ----
    const float* Vap = g_Va + (size_t)b * LN * DN;
    float sacc[5][HN];
#pragma unroll
    for (int i = 0; i < 5; i++)
#pragma unroll
        for (int j = 0; j < HN; j++) sacc[i][j] = 0.f;
    const int R0 = wid * 5;

    for (int j = 0; j < 8; j++) {
        __syncthreads();
        for (int s = tid; s < 1024; s += 256) {   // stage Va[32][132], rows>=30 zeroed
            int l = s >> 5, c4 = (s & 31) << 2;
            float4 v = make_float4(0.f, 0.f, 0.f, 0.f);
            if (l < LN) v = *(const float4*)(Vap + (size_t)l * DN + (j << 7) + c4);
            float* dst = stage + l * 132 + c4;
            dst[0] = v.x; dst[1] = v.y; dst[2] = v.z; dst[3] = v.w;
        }
        __syncthreads();
        const int e0 = (j << 7) + (lane << 2);
        float4 bb = *(const float4*)(b1a + e0);
        float h[5][4];
#pragma unroll
        for (int r5 = 0; r5 < 5; r5++) {
            h[r5][0] = bb.x; h[r5][1] = bb.y; h[r5][2] = bb.z; h[r5][3] = bb.w;
        }
#pragma unroll
        for (int l4 = 0; l4 < 8; l4++) {
            float4 va[4];
#pragma unroll
            for (int il = 0; il < 4; il++)
                va[il] = *(const float4*)&stage[(l4 * 4 + il) * 132 + (lane << 2)];
#pragma unroll
            for (int r5 = 0; r5 < 5; r5++) {
                float4 p = *(const float4*)&p2s[R0 + r5][l4 << 2];
                h[r5][0] += p.x * va[0].x + p.y * va[1].x + p.z * va[2].x + p.w * va[3].x;
                h[r5][1] += p.x * va[0].y + p.y * va[1].y + p.z * va[2].y + p.w * va[3].y;
                h[r5][2] += p.x * va[0].z + p.y * va[1].z + p.z * va[2].z + p.w * va[3].z;
                h[r5][3] += p.x * va[0].w + p.y * va[1].w + p.z * va[2].w + p.w * va[3].w;
            }
        }
        float4 w0 = *(const float4*)(w2a + 0 * DN + e0);
        float4 w1 = *(const float4*)(w2a + 1 * DN + e0);
        float4 w2 = *(const float4*)(w2a + 2 * DN + e0);
        float4 w3 = *(const float4*)(w2a + 3 * DN + e0);
#pragma unroll
        for (int r5 = 0; r5 < 5; r5++) {
            float h0 = fmaxf(h[r5][0], 0.f), h1 = fmaxf(h[r5][1], 0.f);
            float h2 = fmaxf(h[r5][2], 0.f), h3 = fmaxf(h[r5][3], 0.f);
            sacc[r5][0] += h0 * w0.x + h1 * w0.y + h2 * w0.z + h3 * w0.w;
            sacc[r5][1] += h0 * w1.x + h1 * w1.y + h2 * w1.z + h3 * w1.w;
            sacc[r5][2] += h0 * w2.x + h1 * w2.y + h2 * w2.z + h3 * w2.w;
            sacc[r5][3] += h0 * w3.x + h1 * w3.y + h2 * w3.z + h3 * w3.w;
        }
    }
#pragma unroll
    for (int r5 = 0; r5 < 5; r5++)
#pragma unroll
        for (int hh = 0; hh < HN; hh++) {
            float v = sacc[r5][hh];
#pragma unroll
            for (int off = 16; off; off >>= 1) v += __shfl_xor_sync(0xffffffffu, v, off);
            if (lane == 0) s_a[R0 + r5][hh] = v + b2a[hh];
        }

    // ---------------- phase 3b: mirror for words ------------------------------
    const float* Vbp = g_Vb + (size_t)a * RN * DN;
    float sbac[4][HN];
#pragma unroll
    for (int i = 0; i < 4; i++)
#pragma unroll
        for (int j = 0; j < HN; j++) sbac[i][j] = 0.f;
    const int L0 = wid * 4;

    for (int j = 0; j < 8; j++) {
        __syncthreads();
        for (int s = tid; s < 1280; s += 256) {   // stage Vb[40][132], rows>=36 zeroed
            int r = s >> 5, c4 = (s & 31) << 2;
            float4 v = make_float4(0.f, 0.f, 0.f, 0.f);
            if (r < RN) v = *(const float4*)(Vbp + (size_t)r * DN + (j << 7) + c4);
            float* dst = stage + r * 132 + c4;
            dst[0] = v.x; dst[1] = v.y; dst[2] = v.z; dst[3] = v.w;
        }
        __syncthreads();
        const int e0 = (j << 7) + (lane << 2);
        float4 bb = *(const float4*)(b1b + e0);
        float h[4][4];
#pragma unroll
        for (int l4 = 0; l4 < 4; l4++) {
            h[l4][0] = bb.x; h[l4][1] = bb.y; h[l4][2] = bb.z; h[l4][3] = bb.w;
        }
#pragma unroll
        for (int r4 = 0; r4 < 10; r4++) {
            float4 vb[4];
#pragma unroll
            for (int il = 0; il < 4; il++)
                vb[il] = *(const float4*)&stage[(r4 * 4 + il) * 132 + (lane << 2)];
#pragma unroll
            for (int l4 = 0; l4 < 4; l4++) {
                float4 p = *(const float4*)&p1s[L0 + l4][r4 << 2];
                h[l4][0] += p.x * vb[0].x + p.y * vb[1].x + p.z * vb[2].x + p.w * vb[3].x;
                h[l4][1] += p.x * vb[0].y + p.y * vb[1].y + p.z * vb[2].y + p.w * vb[3].y;
                h[l4][2] += p.x * vb[0].z + p.y * vb[1].z + p.z * vb[2].z + p.w * vb[3].z;
                h[l4][3] += p.x * vb[0].w + p.y * vb[1].w + p.z * vb[2].w + p.w * vb[3].w;
            }
        }
        float4 w0 = *(const float4*)(w2b + 0 * DN + e0);
        float4 w1 = *(const float4*)(w2b + 1 * DN + e0);
        float4 w2 = *(const float4*)(w2b + 2 * DN + e0);
        float4 w3 = *(const float4*)(w2b + 3 * DN + e0);
#pragma unroll
        for (int l4 = 0; l4 < 4; l4++) {
            float h0 = fmaxf(h[l4][0], 0.f), h1 = fmaxf(h[l4][1], 0.f);
            float h2 = fmaxf(h[l4][2], 0.f), h3 = fmaxf(h[l4][3], 0.f);
            sbac[l4][0] += h0 * w0.x + h1 * w0.y + h2 * w0.z + h3 * w0.w;
            sbac[l4][1] += h0 * w1.x + h1 * w1.y + h2 * w1.z + h3 * w1.w;
            sbac[l4][2] += h0 * w2.x + h1 * w2.y + h2 * w2.z + h3 * w2.w;
            sbac[l4][3] += h0 * w3.x + h1 * w3.y + h2 * w3.z + h3 * w3.w;
        }
    }
#pragma unroll
    for (int l4 = 0; l4 < 4; l4++)
#pragma unroll
        for (int hh = 0; hh < HN; hh++) {
            float v = sbac[l4][hh];
#pragma unroll
            for (int off = 16; off; off >>= 1) v += __shfl_xor_sync(0xffffffffu, v, off);
            if (lane == 0) s_b[L0 + l4][hh] = v + b2b[hh];
        }
    __syncthreads();

    // ---------------- phase 4: head softmax + combine weights -----------------
    if (tid < HN) {
        int hh = tid;
        float m = -1e30f;
        for (int n = 0; n < RN; n++) m = fmaxf(m, s_a[n][hh]);
        float s = 0.f;
        for (int n = 0; n < RN; n++) s += __expf(s_a[n][hh] - m);
        float inv = 1.f / s;
        for (int n = 0; n < RN; n++) p_a[hh][n] = __expf(s_a[n][hh] - m) * inv;
    }
    if (tid >= 32 && tid < 32 + HN) {
        int hh = tid - 32;
        float m = -1e30f;
        for (int n = 0; n < LN; n++) m = fmaxf(m, s_b[n][hh]);
        float s = 0.f;
        for (int n = 0; n < LN; n++) s += __expf(s_b[n][hh] - m);
        float inv = 1.f / s;
        for (int n = 0; n < LN; n++) p_b[hh][n] = __expf(s_b[n][hh] - m) * inv;
    }
    __syncthreads();
    if (tid < RN)
        qa[tid] = 0.25f * (p_a[0][tid] + p_a[1][tid] + p_a[2][tid] + p_a[3][tid]);
    if (tid >= 64 && tid < 64 + LN) {
        int l = tid - 64;
        qb[l] = 0.25f * (p_b[0][l] + p_b[1][l] + p_b[2][l] + p_b[3][l]);
    }
    __syncthreads();
    if (tid < LN) {
        float s = 0.f;
        for (int n = 0; n < RN; n++) s += qa[n] * p2s[n][tid];
        qbar_a[tid] = s;
    }
    if (tid >= 32 && tid < 32 + RN) {
        int r = tid - 32;
        float s = 0.f;
        for (int l = 0; l < LN; l++) s += qb[l] * p1s[l][r];
        qbar_b[r] = s;
    }
    __syncthreads();

    // ---------------- phase 5: u_a = qbar_a@v2[b], u_b = qbar_b@v1[a], cosine -
    const float* v2p = v2 + (size_t)b * LN * DN;
    const float* v1p = v1 + (size_t)a * RN * DN;
    const int e0 = tid << 2;
    float4 ua = make_float4(0.f, 0.f, 0.f, 0.f);
    float4 ub = make_float4(0.f, 0.f, 0.f, 0.f);
    for (int l = 0; l < LN; l++) {
        float q = qbar_a[l];
        float4 v = *(const float4*)(v2p + (size_t)l * DN + e0);
        ua.x += q * v.x; ua.y += q * v.y; ua.z += q * v.z; ua.w += q * v.w;
    }
    for (int r = 0; r < RN; r++) {
        float q = qbar_b[r];
        float4 v = *(const float4*)(v1p + (size_t)r * DN + e0);
        ub.x += q * v.x; ub.y += q * v.y; ub.z += q * v.z; ub.w += q * v.w;
    }
    float da = ua.x * ub.x + ua.y * ub.y + ua.z * ub.z + ua.w * ub.w;
    float na = ua.x * ua.x + ua.y * ua.y + ua.z * ua.z + ua.w * ua.w;
    float nb = ub.x * ub.x + ub.y * ub.y + ub.z * ub.z + ub.w * ub.w;
#pragma unroll
    for (int off = 16; off; off >>= 1) {
        da += __shfl_xor_sync(0xffffffffu, da, off);
        na += __shfl_xor_sync(0xffffffffu, na, off);
        nb += __shfl_xor_sync(0xffffffffu, nb, off);
    }
    if (lane == 0) { red[wid] = da; red[8 + wid] = na; red[16 + wid] = nb; }
    __syncthreads();
    if (tid == 0) {
        float D = 0.f, Na = 0.f, Nb = 0.f;
        for (int w = 0; w < 8; w++) { D += red[w]; Na += red[8 + w]; Nb += red[16 + w]; }
        out[a * B2N + b] = D / ((sqrtf(Na) + EPSV) * (sqrtf(Nb) + EPSV));
    }
}

extern "C" void kernel_launch(void* const* d_in, const int* in_sizes, int n_in,
                              void* d_out, int out_size) {
    const float* v1   = (const float*)d_in[0];
    const float* v2   = (const float*)d_in[1];
    const float* wimg = (const float*)d_in[2];
    const float* wtxt = (const float*)d_in[3];
    const float* w1a  = (const float*)d_in[4];
    const float* b1a  = (const float*)d_in[5];
    const float* w2a  = (const float*)d_in[6];
    const float* b2a  = (const float*)d_in[7];
    const float* w1b  = (const float*)d_in[8];
    const float* b1b  = (const float*)d_in[9];
    const float* w2b  = (const float*)d_in[10];
    const float* b2b  = (const float*)d_in[11];
    float* out = (float*)d_out;

    // 1) 4 fused pre-GEMMs (N=1024): grid z picks operand set
    dim3 gp(DN / GT, (SM + GT - 1) / GT, 4);          // (8, 14, 4)
    gemm_pre4_kernel<<<gp, 256>>>(v1, v2, wimg, wtxt, w1a, w1b);

    // 2) S-GEMM: g_S = g_k1 @ g_k2^T / 32
    dim3 gs((SN + GT - 1) / GT, (SM + GT - 1) / GT);  // (12, 14)
    gemm_s_kernel<<<gs, 256>>>();

    // 3) per-pair kernel
    pair_kernel<<<dim3(B2N, B1N), 256>>>(v1, v2, w2a, b1a, b2a, w2b, b1b, b2b, out);
    (void)in_sizes; (void)n_in; (void)out_size;
}

// round 17
// speedup vs baseline: 1.0732x; 1.0388x over previous
#include <cuda_runtime.h>
#include <math.h>

#define B1N 48
#define B2N 48
#define RN 36
#define LN 30
#define DN 1024
#define HN 4
#define EPSV 1e-8f
#define SM 1728           // B1N*RN
#define SN 1440           // B2N*LN

// Scratch (static device globals: allocation-free)
__device__ float g_k1[B1N * RN * DN];  // v1 @ w_img^T
__device__ float g_k2[B2N * LN * DN];  // v2 @ w_txt^T
__device__ float g_Vb[B1N * RN * DN];  // v1 @ w1b^T
__device__ float g_Va[B2N * LN * DN];  // v2 @ w1a^T
__device__ float g_S [SM * SN];        // k1_flat @ k2_flat^T / 32

typedef unsigned long long u64t;

// packed f32x2 helpers (sm_103a FFMA2 path — ptxas never emits this itself)
__device__ __forceinline__ u64t pack_dup(float x) {
    u64t r; asm("mov.b64 %0, {%1, %1};" : "=l"(r) : "f"(x)); return r;
}
__device__ __forceinline__ void ffma2(u64t& d, u64t a, u64t b) {
    asm("fma.rn.f32x2 %0, %1, %2, %0;" : "+l"(d) : "l"(a), "l"(b));
}
__device__ __forceinline__ void unpack2(float& lo, float& hi, u64t v) {
    asm("mov.b64 {%0, %1}, %2;" : "=f"(lo), "=f"(hi) : "l"(v));
}

#define GT 128
#define GK 16
#define GP 132

// ---------------------------------------------------------------------------
// 128x128 tile, 8x8/thread (pre4 path) — unchanged from R16 passing kernel.
// ---------------------------------------------------------------------------
__device__ __forceinline__ void gemm_core(
    const float* __restrict__ A, const float* __restrict__ B, float* __restrict__ C,
    int M, int N, float scale, int row0, int col0)
{
    __shared__ __align__(16) float As[GK][GP];
    __shared__ __align__(16) float Bs[GK][GP];

    const int tid = threadIdx.x;
    const int lr = tid >> 1;            // 0..127
    const int lk = (tid & 1) << 3;      // 0 or 8
    const int tx = tid & 15, ty = tid >> 4;

    u64t acc2[8][4];
#pragma unroll
    for (int i = 0; i < 8; i++)
#pragma unroll
        for (int j = 0; j < 4; j++) acc2[i][j] = 0ull;

    const int arow = row0 + lr;
    const int brow = col0 + lr;
    const bool aval = arow < M;
    const bool bval = brow < N;
    const float4 z4 = make_float4(0.f, 0.f, 0.f, 0.f);

    for (int k0 = 0; k0 < DN; k0 += GK) {
        float4 av0 = z4, av1 = z4, bv0 = z4, bv1 = z4;
        if (aval) {
            av0 = *(const float4*)(A + (size_t)arow * DN + k0 + lk);
            av1 = *(const float4*)(A + (size_t)arow * DN + k0 + lk + 4);
        }
        if (bval) {
            bv0 = *(const float4*)(B + (size_t)brow * DN + k0 + lk);
            bv1 = *(const float4*)(B + (size_t)brow * DN + k0 + lk + 4);
        }
        __syncthreads();
        As[lk + 0][lr] = av0.x; As[lk + 1][lr] = av0.y; As[lk + 2][lr] = av0.z; As[lk + 3][lr] = av0.w;
        As[lk + 4][lr] = av1.x; As[lk + 5][lr] = av1.y; As[lk + 6][lr] = av1.z; As[lk + 7][lr] = av1.w;
        Bs[lk + 0][lr] = bv0.x; Bs[lk + 1][lr] = bv0.y; Bs[lk + 2][lr] = bv0.z; Bs[lk + 3][lr] = bv0.w;
        Bs[lk + 4][lr] = bv1.x; Bs[lk + 5][lr] = bv1.y; Bs[lk + 6][lr] = bv1.z; Bs[lk + 7][lr] = bv1.w;
        __syncthreads();

#pragma unroll
        for (int k = 0; k < GK; k++) {
            float4 al = *(const float4*)&As[k][ty << 3];
            float4 ah = *(const float4*)&As[k][(ty << 3) + 4];
            ulonglong2 bl2 = *(const ulonglong2*)&Bs[k][tx << 3];
            ulonglong2 bh2 = *(const ulonglong2*)&Bs[k][(tx << 3) + 4];
            u64t b2[4] = {bl2.x, bl2.y, bh2.x, bh2.y};
            float ar[8] = {al.x, al.y, al.z, al.w, ah.x, ah.y, ah.z, ah.w};
#pragma unroll
            for (int i = 0; i < 8; i++) {
                u64t ad = pack_dup(ar[i]);
#pragma unroll
                for (int jp = 0; jp < 4; jp++) ffma2(acc2[i][jp], ad, b2[jp]);
            }
        }
    }
#pragma unroll
    for (int i = 0; i < 8; i++) {
        int r = row0 + (ty << 3) + i;
        if (r < M) {
            int c = col0 + (tx << 3);
            if (c < N) {
                float cv[8];
#pragma unroll
                for (int jp = 0; jp < 4; jp++)
                    unpack2(cv[2 * jp], cv[2 * jp + 1], acc2[i][jp]);
                *(float4*)(C + (size_t)r * N + c) =
                    make_float4(cv[0] * scale, cv[1] * scale, cv[2] * scale, cv[3] * scale);
                *(float4*)(C + (size_t)r * N + c + 4) =
                    make_float4(cv[4] * scale, cv[5] * scale, cv[6] * scale, cv[7] * scale);
            }
        }
    }
}

// ---------------------------------------------------------------------------
// 128x64 tile, 8x4/thread variant for the S-GEMM: halves per-CTA critical
// path so the single-wave launch finishes ~2x sooner; lower regs -> 3 CTAs/SM.
// Per-output k-order identical to the 128x128 core -> g_S bitwise unchanged.
// ---------------------------------------------------------------------------
#define GPN 68

__device__ __forceinline__ void gemm_core_n64(
    const float* __restrict__ A, const float* __restrict__ B, float* __restrict__ C,
    int M, int N, float scale, int row0, int col0)
{
    __shared__ __align__(16) float As[GK][GP];
    __shared__ __align__(16) float Bs[GK][GPN];

    const int tid = threadIdx.x;
    const int lr = tid >> 1;            // A loader: 0..127
    const int lk = (tid & 1) << 3;      // 0 or 8
    const int rb = tid & 63;            // B loader: row 0..63
    const int kb = ((tid >> 6) & 3) << 2; // 0,4,8,12
    const int tx = tid & 15, ty = tid >> 4;

    u64t acc2[8][2];
#pragma unroll
    for (int i = 0; i < 8; i++) { acc2[i][0] = 0ull; acc2[i][1] = 0ull; }

    const int arow = row0 + lr;
    const int brow = col0 + rb;
    const bool aval = arow < M;
    const bool bval = brow < N;
    const float4 z4 = make_float4(0.f, 0.f, 0.f, 0.f);

    for (int k0 = 0; k0 < DN; k0 += GK) {
        float4 av0 = z4, av1 = z4, bv = z4;
        if (aval) {
            av0 = *(const float4*)(A + (size_t)arow * DN + k0 + lk);
            av1 = *(const float4*)(A + (size_t)arow * DN + k0 + lk + 4);
        }
        if (bval) bv = *(const float4*)(B + (size_t)brow * DN + k0 + kb);
        __syncthreads();
        As[lk + 0][lr] = av0.x; As[lk + 1][lr] = av0.y; As[lk + 2][lr] = av0.z; As[lk + 3][lr] = av0.w;
        As[lk + 4][lr] = av1.x; As[lk + 5][lr] = av1.y; As[lk + 6][lr] = av1.z; As[lk + 7][lr] = av1.w;
        Bs[kb + 0][rb] = bv.x; Bs[kb + 1][rb] = bv.y; Bs[kb + 2][rb] = bv.z; Bs[kb + 3][rb] = bv.w;
        __syncthreads();

#pragma unroll
        for (int k = 0; k < GK; k++) {
            float4 al = *(const float4*)&As[k][ty << 3];
            float4 ah = *(const float4*)&As[k][(ty << 3) + 4];
            ulonglong2 bp = *(const ulonglong2*)&Bs[k][tx << 2];
            float ar[8] = {al.x, al.y, al.z, al.w, ah.x, ah.y, ah.z, ah.w};
#pragma unroll
            for (int i = 0; i < 8; i++) {
                u64t ad = pack_dup(ar[i]);
                ffma2(acc2[i][0], ad, bp.x);
                ffma2(acc2[i][1], ad, bp.y);
            }
        }
    }
#pragma unroll
    for (int i = 0; i < 8; i++) {
        int r = row0 + (ty << 3) + i;
        if (r < M) {
            int c = col0 + (tx << 2);
            if (c < N) {   // c is 4-aligned and N%4==0, so full float4 in-range
                float cv[4];
                unpack2(cv[0], cv[1], acc2[i][0]);
                unpack2(cv[2], cv[3], acc2[i][1]);
                *(float4*)(C + (size_t)r * N + c) =
                    make_float4(cv[0] * scale, cv[1] * scale, cv[2] * scale, cv[3] * scale);
            }
        }
    }
}

// 4 fused pre-GEMMs: z=0: g_k1=v1@wimg^T  z=1: g_Vb=v1@w1b^T
//                    z=2: g_k2=v2@wtxt^T  z=3: g_Va=v2@w1a^T   (all N=1024)
__global__ __launch_bounds__(256, 2) void gemm_pre4_kernel(
    const float* __restrict__ v1, const float* __restrict__ v2,
    const float* __restrict__ wimg, const float* __restrict__ wtxt,
    const float* __restrict__ w1a, const float* __restrict__ w1b)
{
    const int z = blockIdx.z;
    const float* A = (z < 2) ? v1 : v2;
    const float* B = (z == 0) ? wimg : (z == 1) ? w1b : (z == 2) ? wtxt : w1a;
    float* C = (z == 0) ? g_k1 : (z == 1) ? g_Vb : (z == 2) ? g_k2 : g_Va;
    const int M = (z < 2) ? SM : SN;
    const int row0 = blockIdx.y * GT;
    if (row0 >= M) return;
    gemm_core(A, B, C, M, DN, 1.0f, row0, blockIdx.x * GT);
}

// S-GEMM: g_S[1728,1440] = g_k1_flat @ g_k2_flat^T / 32   (128x64 tiles)
__global__ __launch_bounds__(256, 3) void gemm_s_kernel()
{
    gemm_core_n64(g_k1, g_k2, g_S, SM, SN, 0.03125f, blockIdx.y * GT, blockIdx.x * 64);
}

// ---------------------------------------------------------------------------
// One block per (a,b) pair. 256 threads. Phase 1 replaced by g_S load.
// ---------------------------------------------------------------------------
__global__ __launch_bounds__(256) void pair_kernel(
    const float* __restrict__ v1, const float* __restrict__ v2,
    const float* __restrict__ w2a, const float* __restrict__ b1a,
    const float* __restrict__ b2a, const float* __restrict__ w2b,
    const float* __restrict__ b1b, const float* __restrict__ b2b,
    float* __restrict__ out)
{
    const int a = blockIdx.y, b = blockIdx.x;
    const int tid = threadIdx.x;
    const int lane = tid & 31, wid = tid >> 5;

    __shared__ __align__(16) float Ssm[RN][33];
    __shared__ __align__(16) float p2s[40][32];   // softmax over l, rows r (padded)
    __shared__ __align__(16) float p1s[32][40];   // softmax over r, rows l (padded)
    __shared__ __align__(16) float stage[5280];   // phase-3 staging
    __shared__ float s_a[40][HN];
    __shared__ float s_b[32][HN];
    __shared__ float p_a[HN][RN];
    __shared__ float p_b[HN][LN];
    __shared__ float qa[RN];
    __shared__ float qb[LN];
    __shared__ float qbar_a[LN];
    __shared__ float qbar_b[RN];
    __shared__ float red[24];

    // zero padded probability matrices (pad rows/cols must stay exactly 0)
    for (int i = tid; i < 40 * 32; i += 256) ((float*)p2s)[i] = 0.f;
    for (int i = tid; i < 32 * 40; i += 256) ((float*)p1s)[i] = 0.f;

    // ---------------- phase 1': load S tile from g_S -------------------------
    for (int i = tid; i < RN * LN; i += 256) {
        int r = i / LN, l = i - r * LN;
        Ssm[r][l] = g_S[(size_t)(a * RN + r) * SN + b * LN + l];
    }
    __syncthreads();

    // ---------------- phase 2: the two attention softmaxes -------------------
    if (tid < RN) {  // rows -> p2[r][l]
        int r = tid;
        float m = -1e30f;
        for (int l = 0; l < LN; l++) m = fmaxf(m, Ssm[r][l]);
        float s = 0.f;
        for (int l = 0; l < LN; l++) s += __expf(Ssm[r][l] - m);
        float inv = 1.f / s;
        for (int l = 0; l < LN; l++) p2s[r][l] = __expf(Ssm[r][l] - m) * inv;
    }
    if (tid >= 64 && tid < 64 + LN) {  // cols -> p1[l][r]
        int l = tid - 64;
        float m = -1e30f;
        for (int r = 0; r < RN; r++) m = fmaxf(m, Ssm[r][l]);
        float s = 0.f;
        for (int r = 0; r < RN; r++) s += __expf(Ssm[r][l] - m);
        float inv = 1.f / s;
        for (int r = 0; r < RN; r++) p1s[l][r] = __expf(Ssm[r][l] - m) * inv;
    }

    // ---------------- phase 3a: s_a[r][h] = sum_e relu(P2@Va + b1a) * w2a ----
    const float* Vap = g_Va + (size_t)b * LN * DN;
    float sacc[5][HN];
#pragma unroll
    for (int i = 0; i < 5; i++)
#pragma unroll
        for (int j = 0; j < HN; j++) sacc[i][j] = 0.f;
    const int R0 = wid * 5;

    for (int j = 0; j < 8; j++) {
        __syncthreads();
        for (int s = tid; s < 1024; s += 256) {   // stage Va[32][132], rows>=30 zeroed
            int l = s >> 5, c4 = (s & 31) << 2;
            float4 v = make_float4(0.f, 0.f, 0.f, 0.f);
            if (l < LN) v = *(const float4*)(Vap + (size_t)l * DN + (j << 7) + c4);
            float* dst = stage + l * 132 + c4;
            dst[0] = v.x; dst[1] = v.y; dst[2] = v.z; dst[3] = v.w;
        }
        __syncthreads();
        const int e0 = (j << 7) + (lane << 2);
        float4 bb = *(const float4*)(b1a + e0);
        float h[5][4];
#pragma unroll
        for (int r5 = 0; r5 < 5; r5++) {
            h[r5][0] = bb.x; h[r5][1] = bb.y; h[r5][2] = bb.z; h[r5][3] = bb.w;
        }
#pragma unroll
        for (int l4 = 0; l4 < 8; l4++) {
            float4 va[4];
#pragma unroll
            for (int il = 0; il < 4; il++)
                va[il] = *(const float4*)&stage[(l4 * 4 + il) * 132 + (lane << 2)];
#pragma unroll
            for (int r5 = 0; r5 < 5; r5++) {
                float4 p = *(const float4*)&p2s[R0 + r5][l4 << 2];
                h[r5][0] += p.x * va[0].x + p.y * va[1].x + p.z * va[2].x + p.w * va[3].x;
                h[r5][1] += p.x * va[0].y + p.y * va[1].y + p.z * va[2].y + p.w * va[3].y;
                h[r5][2] += p.x * va[0].z + p.y * va[1].z + p.z * va[2].z + p.w * va[3].z;
                h[r5][3] += p.x * va[0].w + p.y * va[1].w + p.z * va[2].w + p.w * va[3].w;
            }
        }
        float4 w0 = *(const float4*)(w2a + 0 * DN + e0);
        float4 w1 = *(const float4*)(w2a + 1 * DN + e0);
        float4 w2 = *(const float4*)(w2a + 2 * DN + e0);
        float4 w3 = *(const float4*)(w2a + 3 * DN + e0);
#pragma unroll
        for (int r5 = 0; r5 < 5; r5++) {
            float h0 = fmaxf(h[r5][0], 0.f), h1 = fmaxf(h[r5][1], 0.f);
            float h2 = fmaxf(h[r5][2], 0.f), h3 = fmaxf(h[r5][3], 0.f);
            sacc[r5][0] += h0 * w0.x + h1 * w0.y + h2 * w0.z + h3 * w0.w;
            sacc[r5][1] += h0 * w1.x + h1 * w1.y + h2 * w1.z + h3 * w1.w;
            sacc[r5][2] += h0 * w2.x + h1 * w2.y + h2 * w2.z + h3 * w2.w;
            sacc[r5][3] += h0 * w3.x + h1 * w3.y + h2 * w3.z + h3 * w3.w;
        }
    }
#pragma unroll
    for (int r5 = 0; r5 < 5; r5++)
#pragma unroll
        for (int hh = 0; hh < HN; hh++) {
            float v = sacc[r5][hh];
#pragma unroll
            for (int off = 16; off; off >>= 1) v += __shfl_xor_sync(0xffffffffu, v, off);
            if (lane == 0) s_a[R0 + r5][hh] = v + b2a[hh];
        }

    // ---------------- phase 3b: mirror for words ------------------------------
    const float* Vbp = g_Vb + (size_t)a * RN * DN;
    float sbac[4][HN];
#pragma unroll
    for (int i = 0; i < 4; i++)
#pragma unroll
        for (int j = 0; j < HN; j++) sbac[i][j] = 0.f;
    const int L0 = wid * 4;

    for (int j = 0; j < 8; j++) {
        __syncthreads();
        for (int s = tid; s < 1280; s += 256) {   // stage Vb[40][132], rows>=36 zeroed
            int r = s >> 5, c4 = (s & 31) << 2;
            float4 v = make_float4(0.f, 0.f, 0.f, 0.f);
            if (r < RN) v = *(const float4*)(Vbp + (size_t)r * DN + (j << 7) + c4);
            float* dst = stage + r * 132 + c4;
            dst[0] = v.x; dst[1] = v.y; dst[2] = v.z; dst[3] = v.w;
        }
        __syncthreads();
        const int e0 = (j << 7) + (lane << 2);
        float4 bb = *(const float4*)(b1b + e0);
        float h[4][4];
#pragma unroll
        for (int l4 = 0; l4 < 4; l4++) {
            h[l4][0] = bb.x; h[l4][1] = bb.y; h[l4][2] = bb.z; h[l4][3] = bb.w;
        }
#pragma unroll
        for (int r4 = 0; r4 < 10; r4++) {
            float4 vb[4];
#pragma unroll
            for (int il = 0; il < 4; il++)
                vb[il] = *(const float4*)&stage[(r4 * 4 + il) * 132 + (lane << 2)];
#pragma unroll
            for (int l4 = 0; l4 < 4; l4++) {
                float4 p = *(const float4*)&p1s[L0 + l4][r4 << 2];
                h[l4][0] += p.x * vb[0].x + p.y * vb[1].x + p.z * vb[2].x + p.w * vb[3].x;
                h[l4][1] += p.x * vb[0].y + p.y * vb[1].y + p.z * vb[2].y + p.w * vb[3].y;
                h[l4][2] += p.x * vb[0].z + p.y * vb[1].z + p.z * vb[2].z + p.w * vb[3].z;
                h[l4][3] += p.x * vb[0].w + p.y * vb[1].w + p.z * vb[2].w + p.w * vb[3].w;
            }
        }
        float4 w0 = *(const float4*)(w2b + 0 * DN + e0);
        float4 w1 = *(const float4*)(w2b + 1 * DN + e0);
        float4 w2 = *(const float4*)(w2b + 2 * DN + e0);
        float4 w3 = *(const float4*)(w2b + 3 * DN + e0);
#pragma unroll
        for (int l4 = 0; l4 < 4; l4++) {
            float h0 = fmaxf(h[l4][0], 0.f), h1 = fmaxf(h[l4][1], 0.f);
            float h2 = fmaxf(h[l4][2], 0.f), h3 = fmaxf(h[l4][3], 0.f);
            sbac[l4][0] += h0 * w0.x + h1 * w0.y + h2 * w0.z + h3 * w0.w;
            sbac[l4][1] += h0 * w1.x + h1 * w1.y + h2 * w1.z + h3 * w1.w;
            sbac[l4][2] += h0 * w2.x + h1 * w2.y + h2 * w2.z + h3 * w2.w;
            sbac[l4][3] += h0 * w3.x + h1 * w3.y + h2 * w3.z + h3 * w3.w;
        }
    }
#pragma unroll
    for (int l4 = 0; l4 < 4; l4++)
#pragma unroll
        for (int hh = 0; hh < HN; hh++) {
            float v = sbac[l4][hh];
#pragma unroll
            for (int off = 16; off; off >>= 1) v += __shfl_xor_sync(0xffffffffu, v, off);
            if (lane == 0) s_b[L0 + l4][hh] = v + b2b[hh];
        }
    __syncthreads();

    // ---------------- phase 4: head softmax + combine weights -----------------
    if (tid < HN) {
        int hh = tid;
        float m = -1e30f;
        for (int n = 0; n < RN; n++) m = fmaxf(m, s_a[n][hh]);
        float s = 0.f;
        for (int n = 0; n < RN; n++) s += __expf(s_a[n][hh] - m);
        float inv = 1.f / s;
        for (int n = 0; n < RN; n++) p_a[hh][n] = __expf(s_a[n][hh] - m) * inv;
    }
    if (tid >= 32 && tid < 32 + HN) {
        int hh = tid - 32;
        float m = -1e30f;
        for (int n = 0; n < LN; n++) m = fmaxf(m, s_b[n][hh]);
        float s = 0.f;
        for (int n = 0; n < LN; n++) s += __expf(s_b[n][hh] - m);
        float inv = 1.f / s;
        for (int n = 0; n < LN; n++) p_b[hh][n] = __expf(s_b[n][hh] - m) * inv;
    }
    __syncthreads();
    if (tid < RN)
        qa[tid] = 0.25f * (p_a[0][tid] + p_a[1][tid] + p_a[2][tid] + p_a[3][tid]);
    if (tid >= 64 && tid < 64 + LN) {
        int l = tid - 64;
        qb[l] = 0.25f * (p_b[0][l] + p_b[1][l] + p_b[2][l] + p_b[3][l]);
    }
    __syncthreads();
    if (tid < LN) {
        float s = 0.f;
        for (int n = 0; n < RN; n++) s += qa[n] * p2s[n][tid];
        qbar_a[tid] = s;
    }
    if (tid >= 32 && tid < 32 + RN) {
        int r = tid - 32;
        float s = 0.f;
        for (int l = 0; l < LN; l++) s += qb[l] * p1s[l][r];
        qbar_b[r] = s;
    }
    __syncthreads();

    // ---------------- phase 5: u_a = qbar_a@v2[b], u_b = qbar_b@v1[a], cosine -
    const float* v2p = v2 + (size_t)b * LN * DN;
    const float* v1p = v1 + (size_t)a * RN * DN;
    const int e0 = tid << 2;
    float4 ua = make_float4(0.f, 0.f, 0.f, 0.f);
    float4 ub = make_float4(0.f, 0.f, 0.f, 0.f);
    for (int l = 0; l < LN; l++) {
        float q = qbar_a[l];
        float4 v = *(const float4*)(v2p + (size_t)l * DN + e0);
        ua.x += q * v.x; ua.y += q * v.y; ua.z += q * v.z; ua.w += q * v.w;
    }
    for (int r = 0; r < RN; r++) {
        float q = qbar_b[r];
        float4 v = *(const float4*)(v1p + (size_t)r * DN + e0);
        ub.x += q * v.x; ub.y += q * v.y; ub.z += q * v.z; ub.w += q * v.w;
    }
    float da = ua.x * ub.x + ua.y * ub.y + ua.z * ub.z + ua.w * ub.w;
    float na = ua.x * ua.x + ua.y * ua.y + ua.z * ua.z + ua.w * ua.w;
    float nb = ub.x * ub.x + ub.y * ub.y + ub.z * ub.z + ub.w * ub.w;
#pragma unroll
    for (int off = 16; off; off >>= 1) {
        da += __shfl_xor_sync(0xffffffffu, da, off);
        na += __shfl_xor_sync(0xffffffffu, na, off);
        nb += __shfl_xor_sync(0xffffffffu, nb, off);
    }
    if (lane == 0) { red[wid] = da; red[8 + wid] = na; red[16 + wid] = nb; }
    __syncthreads();
    if (tid == 0) {
        float D = 0.f, Na = 0.f, Nb = 0.f;
        for (int w = 0; w < 8; w++) { D += red[w]; Na += red[8 + w]; Nb += red[16 + w]; }
        out[a * B2N + b] = D / ((sqrtf(Na) + EPSV) * (sqrtf(Nb) + EPSV));
    }
}

extern "C" void kernel_launch(void* const* d_in, const int* in_sizes, int n_in,
                              void* d_out, int out_size) {
    const float* v1   = (const float*)d_in[0];
    const float* v2   = (const float*)d_in[1];
    const float* wimg = (const float*)d_in[2];
    const float* wtxt = (const float*)d_in[3];
    const float* w1a  = (const float*)d_in[4];
    const float* b1a  = (const float*)d_in[5];
    const float* w2a  = (const float*)d_in[6];
    const float* b2a  = (const float*)d_in[7];
    const float* w1b  = (const float*)d_in[8];
    const float* b1b  = (const float*)d_in[9];
    const float* w2b  = (const float*)d_in[10];
    const float* b2b  = (const float*)d_in[11];
    float* out = (float*)d_out;

    // 1) 4 fused pre-GEMMs (N=1024): grid z picks operand set
    dim3 gp(DN / GT, (SM + GT - 1) / GT, 4);          // (8, 14, 4)
    gemm_pre4_kernel<<<gp, 256>>>(v1, v2, wimg, wtxt, w1a, w1b);

    // 2) S-GEMM: g_S = g_k1 @ g_k2^T / 32, 128x64 tiles -> 322 blocks, 1 wave
    dim3 gs((SN + 63) / 64, (SM + GT - 1) / GT);      // (23, 14)
    gemm_s_kernel<<<gs, 256>>>();

    // 3) per-pair kernel
    pair_kernel<<<dim3(B2N, B1N), 256>>>(v1, v2, w2a, b1a, b2a, w2b, b1b, b2b, out);
    (void)in_sizes; (void)n_in; (void)out_size;
}